// round 2
// baseline (speedup 1.0000x reference)
#include <cuda_runtime.h>

#define NN 50000
#define NE 1600000

// ---------------- scratch (static device globals; no allocs allowed) ----------------
__device__ float g_bufA[NN * 128];
__device__ float g_bufB[NN * 128];
__device__ float g_bufC[NN * 128];
__device__ int   g_rowp[NN + 1];
__device__ int   g_cnt[NN];
__device__ int   g_esrc[NE];

// ---------------- small helpers ----------------
__device__ __forceinline__ void add4(float4& a, float4 v) {
    a.x += v.x; a.y += v.y; a.z += v.z; a.w += v.w;
}
__device__ __forceinline__ void add2(float2& a, float2 v) {
    a.x += v.x; a.y += v.y;
}

// ---------------- CSR build ----------------
__global__ void zero_int_k(int* __restrict__ p, int n) {
    int i = blockIdx.x * blockDim.x + threadIdx.x;
    if (i < n) p[i] = 0;
}

__global__ void count_k(const int* __restrict__ dst, int* __restrict__ cnt, int E) {
    int e = blockIdx.x * blockDim.x + threadIdx.x;
    if (e < E) atomicAdd(&cnt[dst[e]], 1);
}

__global__ void scan_k(const int* __restrict__ cnt, int* __restrict__ rowp, int n) {
    __shared__ int sh[1024];
    __shared__ int carry;
    int t = threadIdx.x;
    if (t == 0) { carry = 0; rowp[0] = 0; }
    __syncthreads();
    for (int base = 0; base < n; base += 1024) {
        int v = (base + t < n) ? cnt[base + t] : 0;
        sh[t] = v;
        __syncthreads();
        for (int off = 1; off < 1024; off <<= 1) {
            int add = (t >= off) ? sh[t - off] : 0;
            __syncthreads();
            sh[t] += add;
            __syncthreads();
        }
        if (base + t < n) rowp[base + t + 1] = carry + sh[t];
        __syncthreads();
        if (t == 0) carry += sh[1023];
        __syncthreads();
    }
}

__global__ void fill_k(const int* __restrict__ src, const int* __restrict__ dst,
                       const int* __restrict__ rowp, int* __restrict__ cursor,
                       int* __restrict__ esrc, int E) {
    int e = blockIdx.x * blockDim.x + threadIdx.x;
    if (e >= E) return;
    int d = dst[e];
    int p = atomicAdd(&cursor[d], 1);
    esrc[rowp[d] + p] = src[e];
}

// ---------------- aggregation kernels (warp per node; z = self + sum_{j->i}) ----------------
__global__ void agg19_k(const float* __restrict__ h, const int* __restrict__ rowp,
                        const int* __restrict__ esrc, float* __restrict__ z, int n) {
    int w = (blockIdx.x * blockDim.x + threadIdx.x) >> 5;
    int lane = threadIdx.x & 31;
    if (w >= n || lane >= 19) return;
    float acc = h[w * 19 + lane];
    int s = rowp[w], e = rowp[w + 1];
    int j = s;
    for (; j + 4 <= e; j += 4) {
        int s0 = esrc[j], s1 = esrc[j + 1], s2 = esrc[j + 2], s3 = esrc[j + 3];
        float a = h[s0 * 19 + lane], b = h[s1 * 19 + lane];
        float c = h[s2 * 19 + lane], d = h[s3 * 19 + lane];
        acc += a; acc += b; acc += c; acc += d;
    }
    for (; j < e; ++j) acc += h[esrc[j] * 19 + lane];
    z[w * 19 + lane] = acc;
}

__global__ void agg128_k(const float* __restrict__ h, const int* __restrict__ rowp,
                         const int* __restrict__ esrc, float* __restrict__ z, int n) {
    int w = (blockIdx.x * blockDim.x + threadIdx.x) >> 5;
    int lane = threadIdx.x & 31;
    if (w >= n) return;
    const float4* h4 = (const float4*)h;
    float4* z4 = (float4*)z;
    float4 acc = h4[w * 32 + lane];
    int s = rowp[w], e = rowp[w + 1];
    int j = s;
    for (; j + 4 <= e; j += 4) {
        int s0 = esrc[j], s1 = esrc[j + 1], s2 = esrc[j + 2], s3 = esrc[j + 3];
        float4 a = h4[s0 * 32 + lane];
        float4 b = h4[s1 * 32 + lane];
        float4 c = h4[s2 * 32 + lane];
        float4 d = h4[s3 * 32 + lane];
        add4(acc, a); add4(acc, b); add4(acc, c); add4(acc, d);
    }
    for (; j < e; ++j) add4(acc, h4[esrc[j] * 32 + lane]);
    z4[w * 32 + lane] = acc;
}

// 64-dim aggregation, fused with +bias and ReLU (layer-3 trick: aggregate after GEMM1)
__global__ void agg64_br_k(const float* __restrict__ h, const int* __restrict__ rowp,
                           const int* __restrict__ esrc, const float* __restrict__ bias,
                           float* __restrict__ z, int n) {
    int w = (blockIdx.x * blockDim.x + threadIdx.x) >> 5;
    int lane = threadIdx.x & 31;
    if (w >= n) return;
    const float2* h2 = (const float2*)h;
    float2* z2 = (float2*)z;
    float2 acc = h2[w * 32 + lane];
    int s = rowp[w], e = rowp[w + 1];
    int j = s;
    for (; j + 4 <= e; j += 4) {
        int s0 = esrc[j], s1 = esrc[j + 1], s2 = esrc[j + 2], s3 = esrc[j + 3];
        float2 a = h2[s0 * 32 + lane];
        float2 b = h2[s1 * 32 + lane];
        float2 c = h2[s2 * 32 + lane];
        float2 d = h2[s3 * 32 + lane];
        add2(acc, a); add2(acc, b); add2(acc, c); add2(acc, d);
    }
    for (; j < e; ++j) add2(acc, h2[esrc[j] * 32 + lane]);
    acc.x += bias[lane * 2];
    acc.y += bias[lane * 2 + 1];
    acc.x = fmaxf(acc.x, 0.0f);
    acc.y = fmaxf(acc.y, 0.0f);
    z2[w * 32 + lane] = acc;
}

// ---------------- GEMM: C[n,OUT] = act(A[n,IN] @ W[IN,OUT] + bias) ----------------
// Block: 256 threads, 64 rows per block. W fully resident in smem, A tile transposed.
// A-tile k-stride padded to TM+4 (=68) so the transpose writes hit 8 banks (4-way
// conflict) instead of 1 bank (32-way), while keeping float4 reads 16B-aligned.
template <int IN, int OUT, bool RELU>
__global__ void gemm_k(const float* __restrict__ A, const float* __restrict__ W,
                       const float* __restrict__ bias, float* __restrict__ C, int n) {
    constexpr int TM = 64;
    constexpr int TMP = TM + 4;         // padded k-stride for As
    constexpr int CT = OUT / 16;        // cols per thread (8 for OUT=128, 4 for OUT=64)
    extern __shared__ float sm[];
    float* Ws = sm;                     // IN*OUT
    float* As = sm + IN * OUT;          // IN*TMP (transposed: As[k*TMP + r])
    float* Bs = As + IN * TMP;          // OUT
    int tid = threadIdx.x;

    for (int i = tid; i < IN * OUT; i += 256) Ws[i] = W[i];
    for (int i = tid; i < OUT; i += 256) Bs[i] = bias ? bias[i] : 0.0f;

    int row0 = blockIdx.x * TM;
    for (int i = tid; i < IN * TM; i += 256) {
        int r = i / IN, k = i % IN;     // coalesced global read along k
        int row = row0 + r;
        As[k * TMP + r] = (row < n) ? A[row * IN + k] : 0.0f;
    }
    __syncthreads();

    int rg = tid >> 4;  // 0..15 -> rows rg*4 .. rg*4+3
    int cg = tid & 15;  // cols cg*CT .. cg*CT+CT-1
    float acc[4][CT];
#pragma unroll
    for (int i = 0; i < 4; ++i)
#pragma unroll
        for (int j = 0; j < CT; ++j) acc[i][j] = 0.0f;

    const float* wbase = Ws + cg * CT;
#pragma unroll 2
    for (int k = 0; k < IN; ++k) {
        float4 a = *(const float4*)(As + k * TMP + rg * 4);
        const float* wrow = wbase + k * OUT;
#pragma unroll
        for (int jj = 0; jj < CT; jj += 4) {
            float4 wv = *(const float4*)(wrow + jj);
            acc[0][jj + 0] += a.x * wv.x; acc[0][jj + 1] += a.x * wv.y;
            acc[0][jj + 2] += a.x * wv.z; acc[0][jj + 3] += a.x * wv.w;
            acc[1][jj + 0] += a.y * wv.x; acc[1][jj + 1] += a.y * wv.y;
            acc[1][jj + 2] += a.y * wv.z; acc[1][jj + 3] += a.y * wv.w;
            acc[2][jj + 0] += a.z * wv.x; acc[2][jj + 1] += a.z * wv.y;
            acc[2][jj + 2] += a.z * wv.z; acc[2][jj + 3] += a.z * wv.w;
            acc[3][jj + 0] += a.w * wv.x; acc[3][jj + 1] += a.w * wv.y;
            acc[3][jj + 2] += a.w * wv.z; acc[3][jj + 3] += a.w * wv.w;
        }
    }

#pragma unroll
    for (int i = 0; i < 4; ++i) {
        int row = row0 + rg * 4 + i;
        if (row < n) {
#pragma unroll
            for (int j = 0; j < CT; ++j) {
                float v = acc[i][j] + Bs[cg * CT + j];
                if (RELU) v = fmaxf(v, 0.0f);
                C[row * OUT + cg * CT + j] = v;
            }
        }
    }
}

// ---------------- heads ----------------
// mmse_pred = LeakyReLU(latent @ m_w + m_b); t_d = latent @ d_w1 (scalar per node)
__global__ void heads_k(const float* __restrict__ latent, const float* __restrict__ m_w,
                        const float* __restrict__ m_b, const float* __restrict__ d_w1,
                        float* __restrict__ mmse_out, float* __restrict__ td, int n) {
    int w = (blockIdx.x * blockDim.x + threadIdx.x) >> 5;
    int lane = threadIdx.x & 31;
    if (w >= n) return;
    float2 l = ((const float2*)latent)[w * 32 + lane];
    float2 mw = ((const float2*)m_w)[lane];
    float2 dw = ((const float2*)d_w1)[lane];
    float dm = l.x * mw.x + l.y * mw.y;
    float dd = l.x * dw.x + l.y * dw.y;
#pragma unroll
    for (int o = 16; o; o >>= 1) {
        dm += __shfl_down_sync(0xffffffffu, dm, o);
        dd += __shfl_down_sync(0xffffffffu, dd, o);
    }
    if (lane == 0) {
        float m = dm + m_b[0];
        mmse_out[w] = (m > 0.0f) ? m : 0.01f * m;
        td[w] = dd;
    }
}

// discrim_out[n] = relu(segsum(td[src]) + td[n] + d_b1) * d_w2 + d_b2
__global__ void discrim_k(const float* __restrict__ td, const int* __restrict__ rowp,
                          const int* __restrict__ esrc, const float* __restrict__ d_b1,
                          const float* __restrict__ d_w2, const float* __restrict__ d_b2,
                          float* __restrict__ out, int n) {
    int i = blockIdx.x * blockDim.x + threadIdx.x;
    if (i >= n) return;
    float acc = td[i];
    int s = rowp[i], e = rowp[i + 1];
    int j = s;
    for (; j + 4 <= e; j += 4) {
        float a = td[esrc[j]], b = td[esrc[j + 1]];
        float c = td[esrc[j + 2]], d = td[esrc[j + 3]];
        acc += a; acc += b; acc += c; acc += d;
    }
    for (; j < e; ++j) acc += td[esrc[j]];
    float u = acc + d_b1[0];
    u = fmaxf(u, 0.0f);
    out[i] = u * d_w2[0] + d_b2[0];
}

// ---------------- host ----------------
template <int IN, int OUT, bool RELU>
static void launch_gemm(const float* A, const float* W, const float* bias, float* C, int n) {
    size_t smb = (size_t)(IN * OUT + IN * 68 + OUT) * sizeof(float);
    cudaFuncSetAttribute(gemm_k<IN, OUT, RELU>,
                         cudaFuncAttributeMaxDynamicSharedMemorySize, (int)smb);
    gemm_k<IN, OUT, RELU><<<(n + 63) / 64, 256, smb>>>(A, W, bias, C, n);
}

extern "C" void kernel_launch(void* const* d_in, const int* in_sizes, int n_in,
                              void* d_out, int out_size) {
    const float* x   = (const float*)d_in[0];
    const int*   ei  = (const int*)d_in[1];
    const int E = in_sizes[1] / 2;
    const int n = in_sizes[0] / 19;
    const int* src = ei;
    const int* dst = ei + E;

    const float* l0w1 = (const float*)d_in[2];
    const float* l0b1 = (const float*)d_in[3];
    const float* l0w2 = (const float*)d_in[4];
    const float* l0b2 = (const float*)d_in[5];
    const float* l1w1 = (const float*)d_in[6];
    const float* l1b1 = (const float*)d_in[7];
    const float* l1w2 = (const float*)d_in[8];
    const float* l1b2 = (const float*)d_in[9];
    const float* l2w1 = (const float*)d_in[10];
    const float* l2b1 = (const float*)d_in[11];
    const float* l2w2 = (const float*)d_in[12];
    const float* l2b2 = (const float*)d_in[13];
    const float* l3w1 = (const float*)d_in[14];
    const float* l3b1 = (const float*)d_in[15];
    const float* l3w2 = (const float*)d_in[16];
    const float* l3b2 = (const float*)d_in[17];
    const float* m_w  = (const float*)d_in[18];
    const float* m_b  = (const float*)d_in[19];
    const float* d_w1 = (const float*)d_in[20];
    const float* d_b1 = (const float*)d_in[21];
    const float* d_w2 = (const float*)d_in[22];
    const float* d_b2 = (const float*)d_in[23];

    void *pA, *pB, *pC, *pRow, *pCnt, *pEsrc;
    cudaGetSymbolAddress(&pA, g_bufA);
    cudaGetSymbolAddress(&pB, g_bufB);
    cudaGetSymbolAddress(&pC, g_bufC);
    cudaGetSymbolAddress(&pRow, g_rowp);
    cudaGetSymbolAddress(&pCnt, g_cnt);
    cudaGetSymbolAddress(&pEsrc, g_esrc);
    float* bufA = (float*)pA;
    float* bufB = (float*)pB;
    float* bufC = (float*)pC;
    int* rowp = (int*)pRow;
    int* cnt  = (int*)pCnt;
    int* esrc = (int*)pEsrc;

    float* out = (float*)d_out;

    const int TB = 256;
    const int edgeBlocks = (E + TB - 1) / TB;
    const int nodeBlocks = (n + TB - 1) / TB;
    const int warpBlocks = (n * 32 + TB - 1) / TB;  // warp per node

    // ---- CSR build ----
    zero_int_k<<<nodeBlocks, TB>>>(cnt, n);
    count_k<<<edgeBlocks, TB>>>(dst, cnt, E);
    scan_k<<<1, 1024>>>(cnt, rowp, n);
    zero_int_k<<<nodeBlocks, TB>>>(cnt, n);
    fill_k<<<edgeBlocks, TB>>>(src, dst, rowp, cnt, esrc, E);

    // ---- layer 0: agg at 19 dims, then MLP ----
    agg19_k<<<warpBlocks, TB>>>(x, rowp, esrc, bufA, n);
    launch_gemm<19, 128, true>(bufA, l0w1, l0b1, bufB, n);
    launch_gemm<128, 128, true>(bufB, l0w2, l0b2, bufC, n);   // + trailing ReLU

    // ---- layer 1 ----
    agg128_k<<<warpBlocks, TB>>>(bufC, rowp, esrc, bufA, n);
    launch_gemm<128, 128, true>(bufA, l1w1, l1b1, bufB, n);
    launch_gemm<128, 128, true>(bufB, l1w2, l1b2, bufC, n);

    // ---- layer 2 ----
    agg128_k<<<warpBlocks, TB>>>(bufC, rowp, esrc, bufA, n);
    launch_gemm<128, 128, true>(bufA, l2w1, l2b1, bufB, n);
    launch_gemm<128, 128, true>(bufB, l2w2, l2b2, bufC, n);

    // ---- layer 3: push aggregation through Linear1 (aggregate at 64 dims) ----
    launch_gemm<128, 64, false>(bufC, l3w1, nullptr, bufA, n);            // y = h2 @ W1
    agg64_br_k<<<warpBlocks, TB>>>(bufA, rowp, esrc, l3b1, bufB, n);      // u = relu(agg(y)+y+b1)
    launch_gemm<64, 64, false>(bufB, l3w2, l3b2, bufC, n);                // latent

    // ---- heads: mmse + discriminator (aggregate at 1 dim) ----
    heads_k<<<warpBlocks, TB>>>(bufC, m_w, m_b, d_w1, out + n, bufA, n);
    discrim_k<<<nodeBlocks, TB>>>(bufA, rowp, esrc, d_b1, d_w2, d_b2, out, n);
}

// round 3
// speedup vs baseline: 1.8633x; 1.8633x over previous
#include <cuda_runtime.h>
#include <cstdint>

#define NN 50000
#define NE 1600000

// ---------------- scratch (static device globals; no allocs allowed) ----------------
__device__ float g_bufA[NN * 128];
__device__ float g_bufB[NN * 128];
__device__ float g_bufC[NN * 128];
__device__ int   g_rowp[NN + 1];
__device__ int   g_cnt[NN];
__device__ int   g_part[NN];
__device__ int   g_bsum[256];
__device__ int   g_esrc[NE];

// ---------------- small helpers ----------------
__device__ __forceinline__ void add4(float4& a, float4 v) {
    a.x += v.x; a.y += v.y; a.z += v.z; a.w += v.w;
}
__device__ __forceinline__ void add2(float2& a, float2 v) {
    a.x += v.x; a.y += v.y;
}
__device__ __forceinline__ uint32_t f2tf(float f) {
    uint32_t r;
    asm("cvt.rna.tf32.f32 %0, %1;" : "=r"(r) : "f"(f));
    return r;
}

// ---------------- CSR build ----------------
__global__ void count_k(const int* __restrict__ dst, int* __restrict__ cnt, int E) {
    int e = blockIdx.x * blockDim.x + threadIdx.x;
    if (e < E) atomicAdd(&cnt[dst[e]], 1);
}

// Phase 1: per-block inclusive scan of 256 elements + block total
__global__ void block_scan_k(const int* __restrict__ cnt, int* __restrict__ part,
                             int* __restrict__ bsum, int n) {
    __shared__ int wsum[8];
    int t = threadIdx.x;
    int i = blockIdx.x * 256 + t;
    int v = (i < n) ? cnt[i] : 0;
    int lane = t & 31, w = t >> 5;
    int x = v;
#pragma unroll
    for (int o = 1; o < 32; o <<= 1) {
        int y = __shfl_up_sync(0xffffffffu, x, o);
        if (lane >= o) x += y;
    }
    if (lane == 31) wsum[w] = x;
    __syncthreads();
    if (w == 0) {
        int s = (lane < 8) ? wsum[lane] : 0;
#pragma unroll
        for (int o = 1; o < 8; o <<= 1) {
            int y = __shfl_up_sync(0xffffffffu, s, o);
            if (lane >= o) s += y;
        }
        if (lane < 8) wsum[lane] = s;
    }
    __syncthreads();
    if (w > 0) x += wsum[w - 1];
    if (i < n) part[i] = x;
    if (t == 255) bsum[blockIdx.x] = x;
}

// Phase 2: exclusive scan of block sums (nb <= 256), in place
__global__ void scan_bsum_k(int* __restrict__ bsum, int nb) {
    __shared__ int wsum[8];
    int t = threadIdx.x;
    int v = (t < nb) ? bsum[t] : 0;
    int lane = t & 31, w = t >> 5;
    int x = v;
#pragma unroll
    for (int o = 1; o < 32; o <<= 1) {
        int y = __shfl_up_sync(0xffffffffu, x, o);
        if (lane >= o) x += y;
    }
    if (lane == 31) wsum[w] = x;
    __syncthreads();
    if (w == 0) {
        int s = (lane < 8) ? wsum[lane] : 0;
#pragma unroll
        for (int o = 1; o < 8; o <<= 1) {
            int y = __shfl_up_sync(0xffffffffu, s, o);
            if (lane >= o) s += y;
        }
        if (lane < 8) wsum[lane] = s;
    }
    __syncthreads();
    if (w > 0) x += wsum[w - 1];
    if (t < nb) bsum[t] = x - v;   // exclusive
}

// Phase 3: rowp[i+1] = part[i] + bsum_ex[i/256]; rowp[0] = 0
__global__ void finalize_rowp_k(const int* __restrict__ part, const int* __restrict__ bsum,
                                int* __restrict__ rowp, int n) {
    int i = blockIdx.x * blockDim.x + threadIdx.x;
    if (i == 0) rowp[0] = 0;
    if (i < n) rowp[i + 1] = part[i] + bsum[i >> 8];
}

__global__ void fill_k(const int* __restrict__ src, const int* __restrict__ dst,
                       const int* __restrict__ rowp, int* __restrict__ cursor,
                       int* __restrict__ esrc, int E) {
    int e = blockIdx.x * blockDim.x + threadIdx.x;
    if (e >= E) return;
    int d = dst[e];
    int p = atomicAdd(&cursor[d], 1);
    esrc[rowp[d] + p] = src[e];
}

// ---------------- aggregation kernels (warp per node; z = self + sum_{j->i}) ----------------
__global__ void agg19_k(const float* __restrict__ h, const int* __restrict__ rowp,
                        const int* __restrict__ esrc, float* __restrict__ z, int n) {
    int w = (blockIdx.x * blockDim.x + threadIdx.x) >> 5;
    int lane = threadIdx.x & 31;
    if (w >= n || lane >= 19) return;
    float acc = h[w * 19 + lane];
    int s = rowp[w], e = rowp[w + 1];
    int j = s;
    for (; j + 4 <= e; j += 4) {
        int s0 = esrc[j], s1 = esrc[j + 1], s2 = esrc[j + 2], s3 = esrc[j + 3];
        float a = h[s0 * 19 + lane], b = h[s1 * 19 + lane];
        float c = h[s2 * 19 + lane], d = h[s3 * 19 + lane];
        acc += a; acc += b; acc += c; acc += d;
    }
    for (; j < e; ++j) acc += h[esrc[j] * 19 + lane];
    z[w * 19 + lane] = acc;
}

__global__ void agg128_k(const float* __restrict__ h, const int* __restrict__ rowp,
                         const int* __restrict__ esrc, float* __restrict__ z, int n) {
    int w = (blockIdx.x * blockDim.x + threadIdx.x) >> 5;
    int lane = threadIdx.x & 31;
    if (w >= n) return;
    const float4* h4 = (const float4*)h;
    float4* z4 = (float4*)z;
    float4 acc = h4[w * 32 + lane];
    int s = rowp[w], e = rowp[w + 1];
    int j = s;
    for (; j + 4 <= e; j += 4) {
        int s0 = esrc[j], s1 = esrc[j + 1], s2 = esrc[j + 2], s3 = esrc[j + 3];
        float4 a = h4[s0 * 32 + lane];
        float4 b = h4[s1 * 32 + lane];
        float4 c = h4[s2 * 32 + lane];
        float4 d = h4[s3 * 32 + lane];
        add4(acc, a); add4(acc, b); add4(acc, c); add4(acc, d);
    }
    for (; j < e; ++j) add4(acc, h4[esrc[j] * 32 + lane]);
    z4[w * 32 + lane] = acc;
}

// 64-dim aggregation, fused with +bias and ReLU (layer-3 trick: aggregate after GEMM1)
__global__ void agg64_br_k(const float* __restrict__ h, const int* __restrict__ rowp,
                           const int* __restrict__ esrc, const float* __restrict__ bias,
                           float* __restrict__ z, int n) {
    int w = (blockIdx.x * blockDim.x + threadIdx.x) >> 5;
    int lane = threadIdx.x & 31;
    if (w >= n) return;
    const float2* h2 = (const float2*)h;
    float2* z2 = (float2*)z;
    float2 acc = h2[w * 32 + lane];
    int s = rowp[w], e = rowp[w + 1];
    int j = s;
    for (; j + 4 <= e; j += 4) {
        int s0 = esrc[j], s1 = esrc[j + 1], s2 = esrc[j + 2], s3 = esrc[j + 3];
        float2 a = h2[s0 * 32 + lane];
        float2 b = h2[s1 * 32 + lane];
        float2 c = h2[s2 * 32 + lane];
        float2 d = h2[s3 * 32 + lane];
        add2(acc, a); add2(acc, b); add2(acc, c); add2(acc, d);
    }
    for (; j < e; ++j) add2(acc, h2[esrc[j] * 32 + lane]);
    acc.x += bias[lane * 2];
    acc.y += bias[lane * 2 + 1];
    acc.x = fmaxf(acc.x, 0.0f);
    acc.y = fmaxf(acc.y, 0.0f);
    z2[w * 32 + lane] = acc;
}

// ---------------- tf32 tensor-core GEMM ----------------
// C[n,OUT] = act(A[n,IN] @ W[IN,OUT] + bias)
// Block: 256 threads (8 warps as 2x4), tile 64 rows x OUT cols, K resident.
// A staged row-major (padded), W staged TRANSPOSED (Ws[n][k], padded) so the
// .row.col mma's col-major B fragment reads are conflict-free.
template <int IN, int OUT, bool RELU>
__global__ void gemm_tc_k(const float* __restrict__ A, const float* __restrict__ W,
                          const float* __restrict__ bias, float* __restrict__ C, int n) {
    constexpr int KP = ((IN + 7) / 8) * 8;   // 24 / 64 / 128
    constexpr int STR = KP + 4;              // padded k-stride (bank-conflict-free frags)
    constexpr int NT = OUT / 32;             // n8-tiles per warp (4 for OUT=128, 2 for 64)
    constexpr int NW = OUT / 4;              // cols per warp

    extern __shared__ uint32_t smu[];
    uint32_t* Ws = smu;                      // [OUT][STR] transposed W in tf32
    uint32_t* As = smu + OUT * STR;          // [64][STR] A tile in tf32
    float* Bs = (float*)(smu + OUT * STR + 64 * STR);  // [OUT] bias

    int tid = threadIdx.x;
    int row0 = blockIdx.x * 64;

    // stage W transposed (+ tf32 convert)
    for (int i = tid; i < IN * OUT; i += 256) {
        int k = i / OUT, nn = i % OUT;       // coalesced read
        Ws[nn * STR + k] = f2tf(W[i]);
    }
    if (KP > IN) {
        for (int i = tid; i < OUT * (KP - IN); i += 256) {
            int nn = i / (KP - IN), k = IN + i % (KP - IN);
            Ws[nn * STR + k] = 0u;
        }
    }
    for (int i = tid; i < OUT; i += 256) Bs[i] = bias ? bias[i] : 0.0f;

    // stage A tile (+ tf32 convert, zero-pad rows/cols)
    for (int i = tid; i < 64 * IN; i += 256) {
        int r = i / IN, k = i % IN;
        int row = row0 + r;
        As[r * STR + k] = (row < n) ? f2tf(A[row * IN + k]) : 0u;
    }
    if (KP > IN) {
        for (int i = tid; i < 64 * (KP - IN); i += 256) {
            int r = i / (KP - IN), k = IN + i % (KP - IN);
            As[r * STR + k] = 0u;
        }
    }
    __syncthreads();

    int w = tid >> 5, lane = tid & 31;
    int wm = w >> 2, wn = w & 3;             // warp grid 2 x 4
    int g = lane >> 2, t4 = lane & 3;

    float acc[2][NT][4];
#pragma unroll
    for (int mt = 0; mt < 2; ++mt)
#pragma unroll
        for (int nt = 0; nt < NT; ++nt)
#pragma unroll
            for (int q = 0; q < 4; ++q) acc[mt][nt][q] = 0.0f;

#pragma unroll
    for (int k0 = 0; k0 < KP; k0 += 8) {
        uint32_t a[2][4];
#pragma unroll
        for (int mt = 0; mt < 2; ++mt) {
            int r = wm * 32 + mt * 16 + g;
            a[mt][0] = As[r * STR + k0 + t4];
            a[mt][1] = As[(r + 8) * STR + k0 + t4];
            a[mt][2] = As[r * STR + k0 + t4 + 4];
            a[mt][3] = As[(r + 8) * STR + k0 + t4 + 4];
        }
        uint32_t b[NT][2];
#pragma unroll
        for (int nt = 0; nt < NT; ++nt) {
            int col = wn * NW + nt * 8 + g;
            b[nt][0] = Ws[col * STR + k0 + t4];
            b[nt][1] = Ws[col * STR + k0 + t4 + 4];
        }
#pragma unroll
        for (int mt = 0; mt < 2; ++mt)
#pragma unroll
            for (int nt = 0; nt < NT; ++nt) {
                asm volatile(
                    "mma.sync.aligned.m16n8k8.row.col.f32.tf32.tf32.f32 "
                    "{%0,%1,%2,%3}, {%4,%5,%6,%7}, {%8,%9}, {%0,%1,%2,%3};\n"
                    : "+f"(acc[mt][nt][0]), "+f"(acc[mt][nt][1]),
                      "+f"(acc[mt][nt][2]), "+f"(acc[mt][nt][3])
                    : "r"(a[mt][0]), "r"(a[mt][1]), "r"(a[mt][2]), "r"(a[mt][3]),
                      "r"(b[nt][0]), "r"(b[nt][1]));
            }
    }

    // epilogue: bias + optional relu, float2 stores
#pragma unroll
    for (int mt = 0; mt < 2; ++mt) {
        int r_lo = row0 + wm * 32 + mt * 16 + g;
#pragma unroll
        for (int nt = 0; nt < NT; ++nt) {
            int col = wn * NW + nt * 8 + t4 * 2;
            float b0 = Bs[col], b1 = Bs[col + 1];
            if (r_lo < n) {
                float v0 = acc[mt][nt][0] + b0;
                float v1 = acc[mt][nt][1] + b1;
                if (RELU) { v0 = fmaxf(v0, 0.0f); v1 = fmaxf(v1, 0.0f); }
                *(float2*)(C + (size_t)r_lo * OUT + col) = make_float2(v0, v1);
            }
            if (r_lo + 8 < n) {
                float v2 = acc[mt][nt][2] + b0;
                float v3 = acc[mt][nt][3] + b1;
                if (RELU) { v2 = fmaxf(v2, 0.0f); v3 = fmaxf(v3, 0.0f); }
                *(float2*)(C + (size_t)(r_lo + 8) * OUT + col) = make_float2(v2, v3);
            }
        }
    }
}

// ---------------- heads ----------------
__global__ void heads_k(const float* __restrict__ latent, const float* __restrict__ m_w,
                        const float* __restrict__ m_b, const float* __restrict__ d_w1,
                        float* __restrict__ mmse_out, float* __restrict__ td, int n) {
    int w = (blockIdx.x * blockDim.x + threadIdx.x) >> 5;
    int lane = threadIdx.x & 31;
    if (w >= n) return;
    float2 l = ((const float2*)latent)[w * 32 + lane];
    float2 mw = ((const float2*)m_w)[lane];
    float2 dw = ((const float2*)d_w1)[lane];
    float dm = l.x * mw.x + l.y * mw.y;
    float dd = l.x * dw.x + l.y * dw.y;
#pragma unroll
    for (int o = 16; o; o >>= 1) {
        dm += __shfl_down_sync(0xffffffffu, dm, o);
        dd += __shfl_down_sync(0xffffffffu, dd, o);
    }
    if (lane == 0) {
        float m = dm + m_b[0];
        mmse_out[w] = (m > 0.0f) ? m : 0.01f * m;
        td[w] = dd;
    }
}

__global__ void discrim_k(const float* __restrict__ td, const int* __restrict__ rowp,
                          const int* __restrict__ esrc, const float* __restrict__ d_b1,
                          const float* __restrict__ d_w2, const float* __restrict__ d_b2,
                          float* __restrict__ out, int n) {
    int i = blockIdx.x * blockDim.x + threadIdx.x;
    if (i >= n) return;
    float acc = td[i];
    int s = rowp[i], e = rowp[i + 1];
    int j = s;
    for (; j + 4 <= e; j += 4) {
        float a = td[esrc[j]], b = td[esrc[j + 1]];
        float c = td[esrc[j + 2]], d = td[esrc[j + 3]];
        acc += a; acc += b; acc += c; acc += d;
    }
    for (; j < e; ++j) acc += td[esrc[j]];
    float u = acc + d_b1[0];
    u = fmaxf(u, 0.0f);
    out[i] = u * d_w2[0] + d_b2[0];
}

// ---------------- host ----------------
template <int IN, int OUT, bool RELU>
static void launch_gemm_tc(const float* A, const float* W, const float* bias, float* C, int n) {
    constexpr int KP = ((IN + 7) / 8) * 8;
    constexpr int STR = KP + 4;
    size_t smb = (size_t)(OUT * STR + 64 * STR) * sizeof(uint32_t) + OUT * sizeof(float);
    cudaFuncSetAttribute(gemm_tc_k<IN, OUT, RELU>,
                         cudaFuncAttributeMaxDynamicSharedMemorySize, (int)smb);
    gemm_tc_k<IN, OUT, RELU><<<(n + 63) / 64, 256, smb>>>(A, W, bias, C, n);
}

extern "C" void kernel_launch(void* const* d_in, const int* in_sizes, int n_in,
                              void* d_out, int out_size) {
    const float* x   = (const float*)d_in[0];
    const int*   ei  = (const int*)d_in[1];
    const int E = in_sizes[1] / 2;
    const int n = in_sizes[0] / 19;
    const int* src = ei;
    const int* dst = ei + E;

    const float* l0w1 = (const float*)d_in[2];
    const float* l0b1 = (const float*)d_in[3];
    const float* l0w2 = (const float*)d_in[4];
    const float* l0b2 = (const float*)d_in[5];
    const float* l1w1 = (const float*)d_in[6];
    const float* l1b1 = (const float*)d_in[7];
    const float* l1w2 = (const float*)d_in[8];
    const float* l1b2 = (const float*)d_in[9];
    const float* l2w1 = (const float*)d_in[10];
    const float* l2b1 = (const float*)d_in[11];
    const float* l2w2 = (const float*)d_in[12];
    const float* l2b2 = (const float*)d_in[13];
    const float* l3w1 = (const float*)d_in[14];
    const float* l3b1 = (const float*)d_in[15];
    const float* l3w2 = (const float*)d_in[16];
    const float* l3b2 = (const float*)d_in[17];
    const float* m_w  = (const float*)d_in[18];
    const float* m_b  = (const float*)d_in[19];
    const float* d_w1 = (const float*)d_in[20];
    const float* d_b1 = (const float*)d_in[21];
    const float* d_w2 = (const float*)d_in[22];
    const float* d_b2 = (const float*)d_in[23];

    void *pA, *pB, *pC, *pRow, *pCnt, *pPart, *pBsum, *pEsrc;
    cudaGetSymbolAddress(&pA, g_bufA);
    cudaGetSymbolAddress(&pB, g_bufB);
    cudaGetSymbolAddress(&pC, g_bufC);
    cudaGetSymbolAddress(&pRow, g_rowp);
    cudaGetSymbolAddress(&pCnt, g_cnt);
    cudaGetSymbolAddress(&pPart, g_part);
    cudaGetSymbolAddress(&pBsum, g_bsum);
    cudaGetSymbolAddress(&pEsrc, g_esrc);
    float* bufA = (float*)pA;
    float* bufB = (float*)pB;
    float* bufC = (float*)pC;
    int* rowp = (int*)pRow;
    int* cnt  = (int*)pCnt;
    int* part = (int*)pPart;
    int* bsum = (int*)pBsum;
    int* esrc = (int*)pEsrc;

    float* out = (float*)d_out;

    const int TB = 256;
    const int edgeBlocks = (E + TB - 1) / TB;
    const int nodeBlocks = (n + TB - 1) / TB;
    const int warpBlocks = (n * 32 + TB - 1) / TB;  // warp per node
    const int nb = (n + 255) / 256;

    // ---- CSR build ----
    cudaMemsetAsync(cnt, 0, (size_t)n * sizeof(int));
    count_k<<<edgeBlocks, TB>>>(dst, cnt, E);
    block_scan_k<<<nb, 256>>>(cnt, part, bsum, n);
    scan_bsum_k<<<1, 256>>>(bsum, nb);
    finalize_rowp_k<<<nodeBlocks, TB>>>(part, bsum, rowp, n);
    cudaMemsetAsync(cnt, 0, (size_t)n * sizeof(int));
    fill_k<<<edgeBlocks, TB>>>(src, dst, rowp, cnt, esrc, E);

    // ---- layer 0: agg at 19 dims, then MLP ----
    agg19_k<<<warpBlocks, TB>>>(x, rowp, esrc, bufA, n);
    launch_gemm_tc<19, 128, true>(bufA, l0w1, l0b1, bufB, n);
    launch_gemm_tc<128, 128, true>(bufB, l0w2, l0b2, bufC, n);  // + trailing ReLU

    // ---- layer 1 ----
    agg128_k<<<warpBlocks, TB>>>(bufC, rowp, esrc, bufA, n);
    launch_gemm_tc<128, 128, true>(bufA, l1w1, l1b1, bufB, n);
    launch_gemm_tc<128, 128, true>(bufB, l1w2, l1b2, bufC, n);

    // ---- layer 2 ----
    agg128_k<<<warpBlocks, TB>>>(bufC, rowp, esrc, bufA, n);
    launch_gemm_tc<128, 128, true>(bufA, l2w1, l2b1, bufB, n);
    launch_gemm_tc<128, 128, true>(bufB, l2w2, l2b2, bufC, n);

    // ---- layer 3: push aggregation through Linear1 (aggregate at 64 dims) ----
    launch_gemm_tc<128, 64, false>(bufC, l3w1, nullptr, bufA, n);         // y = h2 @ W1
    agg64_br_k<<<warpBlocks, TB>>>(bufA, rowp, esrc, l3b1, bufB, n);      // u = relu(agg(y)+y+b1)
    launch_gemm_tc<64, 64, false>(bufB, l3w2, l3b2, bufC, n);             // latent

    // ---- heads: mmse + discriminator (aggregate at 1 dim) ----
    heads_k<<<warpBlocks, TB>>>(bufC, m_w, m_b, d_w1, out + n, bufA, n);
    discrim_k<<<nodeBlocks, TB>>>(bufA, rowp, esrc, d_b1, d_w2, d_b2, out, n);
}

// round 5
// speedup vs baseline: 2.0548x; 1.1028x over previous
#include <cuda_runtime.h>
#include <cuda_fp16.h>
#include <cstdint>

#define NN 50000
#define NE 1600000

// ---------------- scratch (static device globals; no allocs allowed) ----------------
__device__ float  g_bufA[NN * 128];
__device__ float  g_bufB[NN * 128];
__device__ float  g_bufC[NN * 128];
__device__ __half g_h16[NN * 128];
__device__ __half g_x16[NN * 19];
__device__ float  g_vm[64];
__device__ float  g_vd[64];
__device__ float  g_sc[2];
__device__ int    g_rowp[NN + 1];
__device__ int    g_cnt[NN];
__device__ int    g_part[NN];
__device__ int    g_bsum[256];
__device__ int    g_esrc[NE];

// ---------------- small helpers ----------------
__device__ __forceinline__ uint32_t f2tf(float f) {
    uint32_t r;
    asm("cvt.rna.tf32.f32 %0, %1;" : "=r"(r) : "f"(f));
    return r;
}

// ---------------- CSR build ----------------
__global__ void count_k(const int* __restrict__ dst, int* __restrict__ cnt, int E) {
    int e = blockIdx.x * blockDim.x + threadIdx.x;
    if (e < E) atomicAdd(&cnt[dst[e]], 1);
}

__global__ void block_scan_k(const int* __restrict__ cnt, int* __restrict__ part,
                             int* __restrict__ bsum, int n) {
    __shared__ int wsum[8];
    int t = threadIdx.x;
    int i = blockIdx.x * 256 + t;
    int v = (i < n) ? cnt[i] : 0;
    int lane = t & 31, w = t >> 5;
    int x = v;
#pragma unroll
    for (int o = 1; o < 32; o <<= 1) {
        int y = __shfl_up_sync(0xffffffffu, x, o);
        if (lane >= o) x += y;
    }
    if (lane == 31) wsum[w] = x;
    __syncthreads();
    if (w == 0) {
        int s = (lane < 8) ? wsum[lane] : 0;
#pragma unroll
        for (int o = 1; o < 8; o <<= 1) {
            int y = __shfl_up_sync(0xffffffffu, s, o);
            if (lane >= o) s += y;
        }
        if (lane < 8) wsum[lane] = s;
    }
    __syncthreads();
    if (w > 0) x += wsum[w - 1];
    if (i < n) part[i] = x;
    if (t == 255) bsum[blockIdx.x] = x;
}

__global__ void scan_bsum_k(int* __restrict__ bsum, int nb) {
    __shared__ int wsum[8];
    int t = threadIdx.x;
    int v = (t < nb) ? bsum[t] : 0;
    int lane = t & 31, w = t >> 5;
    int x = v;
#pragma unroll
    for (int o = 1; o < 32; o <<= 1) {
        int y = __shfl_up_sync(0xffffffffu, x, o);
        if (lane >= o) x += y;
    }
    if (lane == 31) wsum[w] = x;
    __syncthreads();
    if (w == 0) {
        int s = (lane < 8) ? wsum[lane] : 0;
#pragma unroll
        for (int o = 1; o < 8; o <<= 1) {
            int y = __shfl_up_sync(0xffffffffu, s, o);
            if (lane >= o) s += y;
        }
        if (lane < 8) wsum[lane] = s;
    }
    __syncthreads();
    if (w > 0) x += wsum[w - 1];
    if (t < nb) bsum[t] = x - v;   // exclusive
}

__global__ void finalize_rowp_k(const int* __restrict__ part, const int* __restrict__ bsum,
                                int* __restrict__ rowp, int n) {
    int i = blockIdx.x * blockDim.x + threadIdx.x;
    if (i == 0) rowp[0] = 0;
    if (i < n) rowp[i + 1] = part[i] + bsum[i >> 8];
}

__global__ void fill_k(const int* __restrict__ src, const int* __restrict__ dst,
                       const int* __restrict__ rowp, int* __restrict__ cursor,
                       int* __restrict__ esrc, int E) {
    int e = blockIdx.x * blockDim.x + threadIdx.x;
    if (e >= E) return;
    int d = dst[e];
    int p = atomicAdd(&cursor[d], 1);
    esrc[rowp[d] + p] = src[e];
}

// ---------------- fp32 -> fp16 conversion ----------------
__global__ void f2h_k(const float* __restrict__ x, __half* __restrict__ xh, int n) {
    int i = blockIdx.x * blockDim.x + threadIdx.x;
    if (i < n) xh[i] = __float2half_rn(x[i]);
}

// ---------------- head precompute: v_m = W2@m_w, v_d = W2@d_w1 ----------------
__global__ void precomp_k(const float* __restrict__ W2, const float* __restrict__ b2,
                          const float* __restrict__ m_w, const float* __restrict__ m_b,
                          const float* __restrict__ d_w1,
                          float* __restrict__ vm, float* __restrict__ vd,
                          float* __restrict__ sc) {
    int i = threadIdx.x;  // 64 threads
    float am = 0.0f, ad = 0.0f;
    for (int k = 0; k < 64; ++k) {
        float w = W2[i * 64 + k];
        am += w * m_w[k];
        ad += w * d_w1[k];
    }
    vm[i] = am;
    vd[i] = ad;
    if (i == 0) {
        float sm = m_b[0], sd = 0.0f;
        for (int k = 0; k < 64; ++k) {
            sm += b2[k] * m_w[k];
            sd += b2[k] * d_w1[k];
        }
        sc[0] = sm;
        sc[1] = sd;
    }
}

// ---------------- aggregation kernels (warp per node; z = self + sum_{j->i}) ----------------
__global__ void agg19h_k(const __half* __restrict__ xh, const int* __restrict__ rowp,
                         const int* __restrict__ esrc, float* __restrict__ z, int n) {
    int w = (blockIdx.x * blockDim.x + threadIdx.x) >> 5;
    int lane = threadIdx.x & 31;
    if (w >= n || lane >= 19) return;
    float acc = __half2float(xh[w * 19 + lane]);
    int s = rowp[w], e = rowp[w + 1];
    int j = s;
    for (; j + 4 <= e; j += 4) {
        int s0 = esrc[j], s1 = esrc[j + 1], s2 = esrc[j + 2], s3 = esrc[j + 3];
        float a = __half2float(xh[s0 * 19 + lane]);
        float b = __half2float(xh[s1 * 19 + lane]);
        float c = __half2float(xh[s2 * 19 + lane]);
        float d = __half2float(xh[s3 * 19 + lane]);
        acc += a; acc += b; acc += c; acc += d;
    }
    for (; j < e; ++j) acc += __half2float(xh[esrc[j] * 19 + lane]);
    z[w * 19 + lane] = acc;
}

__device__ __forceinline__ void acc_h4(float4& acc, uint2 v) {
    float2 f0 = __half22float2(*(__half2*)&v.x);
    float2 f1 = __half22float2(*(__half2*)&v.y);
    acc.x += f0.x; acc.y += f0.y; acc.z += f1.x; acc.w += f1.y;
}

// 128-dim fp16 gather, fp32 z out. Each lane covers 4 features (one uint2 = 8B).
__global__ void agg128h_k(const __half* __restrict__ h, const int* __restrict__ rowp,
                          const int* __restrict__ esrc, float* __restrict__ z, int n) {
    int w = (blockIdx.x * blockDim.x + threadIdx.x) >> 5;
    int lane = threadIdx.x & 31;
    if (w >= n) return;
    const uint2* h4 = (const uint2*)h;   // 4 halfs per uint2, 32 per row
    float4 acc = make_float4(0.f, 0.f, 0.f, 0.f);
    acc_h4(acc, h4[w * 32 + lane]);
    int s = rowp[w], e = rowp[w + 1];
    int j = s;
    for (; j + 4 <= e; j += 4) {
        int s0 = esrc[j], s1 = esrc[j + 1], s2 = esrc[j + 2], s3 = esrc[j + 3];
        uint2 a = h4[s0 * 32 + lane];
        uint2 b = h4[s1 * 32 + lane];
        uint2 c = h4[s2 * 32 + lane];
        uint2 d = h4[s3 * 32 + lane];
        acc_h4(acc, a); acc_h4(acc, b); acc_h4(acc, c); acc_h4(acc, d);
    }
    for (; j < e; ++j) acc_h4(acc, h4[esrc[j] * 32 + lane]);
    ((float4*)z)[w * 32 + lane] = acc;
}

// 64-dim fp16 gather + bias + ReLU + fused dual head dot products.
// u = relu(agg(y)+y+b1); mmse = LeakyReLU(u.vm + sc0); td = u.vd + sc1
__global__ void agg64_heads_k(const __half* __restrict__ y, const int* __restrict__ rowp,
                              const int* __restrict__ esrc, const float* __restrict__ bias,
                              const float* __restrict__ vm, const float* __restrict__ vd,
                              const float* __restrict__ sc,
                              float* __restrict__ mmse_out, float* __restrict__ td, int n) {
    int w = (blockIdx.x * blockDim.x + threadIdx.x) >> 5;
    int lane = threadIdx.x & 31;
    if (w >= n) return;
    const __half2* h2 = (const __half2*)y;  // 32 half2 per row
    float2 acc = __half22float2(h2[w * 32 + lane]);
    int s = rowp[w], e = rowp[w + 1];
    int j = s;
    for (; j + 4 <= e; j += 4) {
        int s0 = esrc[j], s1 = esrc[j + 1], s2 = esrc[j + 2], s3 = esrc[j + 3];
        float2 a = __half22float2(h2[s0 * 32 + lane]);
        float2 b = __half22float2(h2[s1 * 32 + lane]);
        float2 c = __half22float2(h2[s2 * 32 + lane]);
        float2 d = __half22float2(h2[s3 * 32 + lane]);
        acc.x += a.x; acc.y += a.y; acc.x += b.x; acc.y += b.y;
        acc.x += c.x; acc.y += c.y; acc.x += d.x; acc.y += d.y;
    }
    for (; j < e; ++j) {
        float2 f = __half22float2(h2[esrc[j] * 32 + lane]);
        acc.x += f.x; acc.y += f.y;
    }
    float ux = fmaxf(acc.x + bias[lane * 2], 0.0f);
    float uy = fmaxf(acc.y + bias[lane * 2 + 1], 0.0f);
    float dm = ux * vm[lane * 2] + uy * vm[lane * 2 + 1];
    float dd = ux * vd[lane * 2] + uy * vd[lane * 2 + 1];
#pragma unroll
    for (int o = 16; o; o >>= 1) {
        dm += __shfl_down_sync(0xffffffffu, dm, o);
        dd += __shfl_down_sync(0xffffffffu, dd, o);
    }
    if (lane == 0) {
        float m = dm + sc[0];
        mmse_out[w] = (m > 0.0f) ? m : 0.01f * m;
        td[w] = dd + sc[1];
    }
}

// discrim_out[n] = relu(segsum(td[src]) + td[n] + d_b1) * d_w2 + d_b2
__global__ void discrim_k(const float* __restrict__ td, const int* __restrict__ rowp,
                          const int* __restrict__ esrc, const float* __restrict__ d_b1,
                          const float* __restrict__ d_w2, const float* __restrict__ d_b2,
                          float* __restrict__ out, int n) {
    int i = blockIdx.x * blockDim.x + threadIdx.x;
    if (i >= n) return;
    float acc = td[i];
    int s = rowp[i], e = rowp[i + 1];
    int j = s;
    for (; j + 4 <= e; j += 4) {
        float a = td[esrc[j]], b = td[esrc[j + 1]];
        float c = td[esrc[j + 2]], d = td[esrc[j + 3]];
        acc += a; acc += b; acc += c; acc += d;
    }
    for (; j < e; ++j) acc += td[esrc[j]];
    float u = acc + d_b1[0];
    u = fmaxf(u, 0.0f);
    out[i] = u * d_w2[0] + d_b2[0];
}

// ---------------- tf32 tensor-core GEMM ----------------
// C[n,OUT] = act(A[n,IN] @ W[IN,OUT] + bias); output fp32 (Cf) or fp16 (Ch).
template <int IN, int OUT, bool RELU, bool HOUT>
__global__ void gemm_tc_k(const float* __restrict__ A, const float* __restrict__ W,
                          const float* __restrict__ bias, float* __restrict__ Cf,
                          __half* __restrict__ Ch, int n) {
    constexpr int KP = ((IN + 7) / 8) * 8;   // 24 / 64 / 128
    constexpr int STR = KP + 4;              // padded k-stride
    constexpr int NT = OUT / 32;             // n8-tiles per warp
    constexpr int NW = OUT / 4;              // cols per warp

    extern __shared__ uint32_t smu[];
    uint32_t* Ws = smu;                      // [OUT][STR] transposed W in tf32
    uint32_t* As = smu + OUT * STR;          // [64][STR] A tile in tf32
    float* Bs = (float*)(smu + OUT * STR + 64 * STR);  // [OUT] bias

    int tid = threadIdx.x;
    int row0 = blockIdx.x * 64;

    for (int i = tid; i < IN * OUT; i += 256) {
        int k = i / OUT, nn = i % OUT;
        Ws[nn * STR + k] = f2tf(W[i]);
    }
    if (KP > IN) {
        for (int i = tid; i < OUT * (KP - IN); i += 256) {
            int nn = i / (KP - IN), k = IN + i % (KP - IN);
            Ws[nn * STR + k] = 0u;
        }
    }
    for (int i = tid; i < OUT; i += 256) Bs[i] = bias ? bias[i] : 0.0f;

    for (int i = tid; i < 64 * IN; i += 256) {
        int r = i / IN, k = i % IN;
        int row = row0 + r;
        As[r * STR + k] = (row < n) ? f2tf(A[row * IN + k]) : 0u;
    }
    if (KP > IN) {
        for (int i = tid; i < 64 * (KP - IN); i += 256) {
            int r = i / (KP - IN), k = IN + i % (KP - IN);
            As[r * STR + k] = 0u;
        }
    }
    __syncthreads();

    int w = tid >> 5, lane = tid & 31;
    int wm = w >> 2, wn = w & 3;             // warp grid 2 x 4
    int g = lane >> 2, t4 = lane & 3;

    float acc[2][NT][4];
#pragma unroll
    for (int mt = 0; mt < 2; ++mt)
#pragma unroll
        for (int nt = 0; nt < NT; ++nt)
#pragma unroll
            for (int q = 0; q < 4; ++q) acc[mt][nt][q] = 0.0f;

#pragma unroll
    for (int k0 = 0; k0 < KP; k0 += 8) {
        uint32_t a[2][4];
#pragma unroll
        for (int mt = 0; mt < 2; ++mt) {
            int r = wm * 32 + mt * 16 + g;
            a[mt][0] = As[r * STR + k0 + t4];
            a[mt][1] = As[(r + 8) * STR + k0 + t4];
            a[mt][2] = As[r * STR + k0 + t4 + 4];
            a[mt][3] = As[(r + 8) * STR + k0 + t4 + 4];
        }
        uint32_t b[NT][2];
#pragma unroll
        for (int nt = 0; nt < NT; ++nt) {
            int col = wn * NW + nt * 8 + g;
            b[nt][0] = Ws[col * STR + k0 + t4];
            b[nt][1] = Ws[col * STR + k0 + t4 + 4];
        }
#pragma unroll
        for (int mt = 0; mt < 2; ++mt)
#pragma unroll
            for (int nt = 0; nt < NT; ++nt) {
                asm volatile(
                    "mma.sync.aligned.m16n8k8.row.col.f32.tf32.tf32.f32 "
                    "{%0,%1,%2,%3}, {%4,%5,%6,%7}, {%8,%9}, {%0,%1,%2,%3};\n"
                    : "+f"(acc[mt][nt][0]), "+f"(acc[mt][nt][1]),
                      "+f"(acc[mt][nt][2]), "+f"(acc[mt][nt][3])
                    : "r"(a[mt][0]), "r"(a[mt][1]), "r"(a[mt][2]), "r"(a[mt][3]),
                      "r"(b[nt][0]), "r"(b[nt][1]));
            }
    }

#pragma unroll
    for (int mt = 0; mt < 2; ++mt) {
        int r_lo = row0 + wm * 32 + mt * 16 + g;
#pragma unroll
        for (int nt = 0; nt < NT; ++nt) {
            int col = wn * NW + nt * 8 + t4 * 2;
            float b0 = Bs[col], b1 = Bs[col + 1];
            if (r_lo < n) {
                float v0 = acc[mt][nt][0] + b0;
                float v1 = acc[mt][nt][1] + b1;
                if (RELU) { v0 = fmaxf(v0, 0.0f); v1 = fmaxf(v1, 0.0f); }
                if (HOUT) *(__half2*)(Ch + (size_t)r_lo * OUT + col) = __floats2half2_rn(v0, v1);
                else      *(float2*)(Cf + (size_t)r_lo * OUT + col) = make_float2(v0, v1);
            }
            if (r_lo + 8 < n) {
                float v2 = acc[mt][nt][2] + b0;
                float v3 = acc[mt][nt][3] + b1;
                if (RELU) { v2 = fmaxf(v2, 0.0f); v3 = fmaxf(v3, 0.0f); }
                if (HOUT) *(__half2*)(Ch + (size_t)(r_lo + 8) * OUT + col) = __floats2half2_rn(v2, v3);
                else      *(float2*)(Cf + (size_t)(r_lo + 8) * OUT + col) = make_float2(v2, v3);
            }
        }
    }
}

// ---------------- host ----------------
template <int IN, int OUT, bool RELU, bool HOUT>
static void launch_gemm_tc(const float* A, const float* W, const float* bias,
                           float* Cf, __half* Ch, int n) {
    constexpr int KP = ((IN + 7) / 8) * 8;
    constexpr int STR = KP + 4;
    size_t smb = (size_t)(OUT * STR + 64 * STR) * sizeof(uint32_t) + OUT * sizeof(float);
    cudaFuncSetAttribute(gemm_tc_k<IN, OUT, RELU, HOUT>,
                         cudaFuncAttributeMaxDynamicSharedMemorySize, (int)smb);
    gemm_tc_k<IN, OUT, RELU, HOUT><<<(n + 63) / 64, 256, smb>>>(A, W, bias, Cf, Ch, n);
}

extern "C" void kernel_launch(void* const* d_in, const int* in_sizes, int n_in,
                              void* d_out, int out_size) {
    const float* x   = (const float*)d_in[0];
    const int*   ei  = (const int*)d_in[1];
    const int E = in_sizes[1] / 2;
    const int n = in_sizes[0] / 19;
    const int* src = ei;
    const int* dst = ei + E;

    const float* l0w1 = (const float*)d_in[2];
    const float* l0b1 = (const float*)d_in[3];
    const float* l0w2 = (const float*)d_in[4];
    const float* l0b2 = (const float*)d_in[5];
    const float* l1w1 = (const float*)d_in[6];
    const float* l1b1 = (const float*)d_in[7];
    const float* l1w2 = (const float*)d_in[8];
    const float* l1b2 = (const float*)d_in[9];
    const float* l2w1 = (const float*)d_in[10];
    const float* l2b1 = (const float*)d_in[11];
    const float* l2w2 = (const float*)d_in[12];
    const float* l2b2 = (const float*)d_in[13];
    const float* l3w1 = (const float*)d_in[14];
    const float* l3b1 = (const float*)d_in[15];
    const float* l3w2 = (const float*)d_in[16];
    const float* l3b2 = (const float*)d_in[17];
    const float* m_w  = (const float*)d_in[18];
    const float* m_b  = (const float*)d_in[19];
    const float* d_w1 = (const float*)d_in[20];
    const float* d_b1 = (const float*)d_in[21];
    const float* d_w2 = (const float*)d_in[22];
    const float* d_b2 = (const float*)d_in[23];

    void *pA, *pB, *pC, *pH, *pX, *pVm, *pVd, *pSc, *pRow, *pCnt, *pPart, *pBsum, *pEsrc;
    cudaGetSymbolAddress(&pA, g_bufA);
    cudaGetSymbolAddress(&pB, g_bufB);
    cudaGetSymbolAddress(&pC, g_bufC);
    cudaGetSymbolAddress(&pH, g_h16);
    cudaGetSymbolAddress(&pX, g_x16);
    cudaGetSymbolAddress(&pVm, g_vm);
    cudaGetSymbolAddress(&pVd, g_vd);
    cudaGetSymbolAddress(&pSc, g_sc);
    cudaGetSymbolAddress(&pRow, g_rowp);
    cudaGetSymbolAddress(&pCnt, g_cnt);
    cudaGetSymbolAddress(&pPart, g_part);
    cudaGetSymbolAddress(&pBsum, g_bsum);
    cudaGetSymbolAddress(&pEsrc, g_esrc);
    float*  bufA = (float*)pA;
    float*  bufB = (float*)pB;
    float*  bufC = (float*)pC;
    __half* h16  = (__half*)pH;
    __half* x16  = (__half*)pX;
    float*  vm   = (float*)pVm;
    float*  vd   = (float*)pVd;
    float*  sc   = (float*)pSc;
    int* rowp = (int*)pRow;
    int* cnt  = (int*)pCnt;
    int* part = (int*)pPart;
    int* bsum = (int*)pBsum;
    int* esrc = (int*)pEsrc;

    float* out = (float*)d_out;

    const int TB = 256;
    const int edgeBlocks = (E + TB - 1) / TB;
    const int nodeBlocks = (n + TB - 1) / TB;
    const int warpBlocks = (n * 32 + TB - 1) / TB;  // warp per node
    const int nb = (n + 255) / 256;

    // ---- independent precomputes ----
    f2h_k<<<(n * 19 + 255) / 256, 256>>>(x, x16, n * 19);
    precomp_k<<<1, 64>>>(l3w2, l3b2, m_w, m_b, d_w1, vm, vd, sc);

    // ---- CSR build ----
    cudaMemsetAsync(cnt, 0, (size_t)n * sizeof(int));
    count_k<<<edgeBlocks, TB>>>(dst, cnt, E);
    block_scan_k<<<nb, 256>>>(cnt, part, bsum, n);
    scan_bsum_k<<<1, 256>>>(bsum, nb);
    finalize_rowp_k<<<nodeBlocks, TB>>>(part, bsum, rowp, n);
    cudaMemsetAsync(cnt, 0, (size_t)n * sizeof(int));
    fill_k<<<edgeBlocks, TB>>>(src, dst, rowp, cnt, esrc, E);

    // ---- layer 0 ----
    agg19h_k<<<warpBlocks, TB>>>(x16, rowp, esrc, bufA, n);
    launch_gemm_tc<19, 128, true, false>(bufA, l0w1, l0b1, bufB, nullptr, n);
    launch_gemm_tc<128, 128, true, true>(bufB, l0w2, l0b2, nullptr, h16, n);  // h0 fp16, relu'd

    // ---- layer 1 ----
    agg128h_k<<<warpBlocks, TB>>>(h16, rowp, esrc, bufA, n);
    launch_gemm_tc<128, 128, true, false>(bufA, l1w1, l1b1, bufB, nullptr, n);
    launch_gemm_tc<128, 128, true, true>(bufB, l1w2, l1b2, nullptr, h16, n);  // h1 fp16, relu'd

    // ---- layer 2 ----
    agg128h_k<<<warpBlocks, TB>>>(h16, rowp, esrc, bufA, n);
    launch_gemm_tc<128, 128, true, false>(bufA, l2w1, l2b1, bufB, nullptr, n);
    launch_gemm_tc<128, 128, true, false>(bufB, l2w2, l2b2, bufC, nullptr, n); // h2 fp32, relu'd

    // ---- layer 3: y = h2 @ W1 (fp16), aggregate at 64, fused heads ----
    launch_gemm_tc<128, 64, false, true>(bufC, l3w1, nullptr, nullptr, h16, n); // y fp16 (reuse h16)
    agg64_heads_k<<<warpBlocks, TB>>>(h16, rowp, esrc, l3b1, vm, vd, sc,
                                      out + n, bufA, n);                        // mmse + td

    // ---- discriminator ----
    discrim_k<<<nodeBlocks, TB>>>(bufA, rowp, esrc, d_b1, d_w2, d_b2, out, n);
}